// round 6
// baseline (speedup 1.0000x reference)
#include <cuda_runtime.h>

#define N_SPH 128
#define N_MAX (1 << 20)
typedef unsigned long long u64;

// -ln(1e-6)/32 : exact output when s clamps at 1e-6
#define FASTVAL 0.4317347049363836f

__device__ float4 g_comp[N_MAX];  // compacted near points (x,y,z, idx-bits)
__device__ int    g_count;        // running compaction counter
__device__ int    g_done;         // classify block-completion ticket
__device__ int    g_total;        // snapshot of final count for main_k
__device__ int    g_ticket;       // dynamic slab ticket for main_k

// ---- packed f32x2 helpers (sm_100+) ----
__device__ __forceinline__ u64 pk2(float lo, float hi) {
    u64 r; asm("mov.b64 %0, {%1, %2};" : "=l"(r) : "f"(lo), "f"(hi)); return r;
}
__device__ __forceinline__ float2 up2(u64 v) {
    float2 f; asm("mov.b64 {%0, %1}, %2;" : "=f"(f.x), "=f"(f.y) : "l"(v)); return f;
}
__device__ __forceinline__ u64 f2fma(u64 a, u64 b, u64 c) {
    u64 d; asm("fma.rn.f32x2 %0, %1, %2, %3;" : "=l"(d) : "l"(a), "l"(b), "l"(c)); return d;
}
__device__ __forceinline__ u64 f2mul(u64 a, u64 b) {
    u64 d; asm("mul.rn.f32x2 %0, %1, %2;" : "=l"(d) : "l"(a), "l"(b)); return d;
}
__device__ __forceinline__ float sqrt_ap(float x) {
    float r; asm("sqrt.approx.f32 %0, %1;" : "=f"(r) : "f"(x)); return r;
}
__device__ __forceinline__ float ex2_ap(float x) {
    float r; asm("ex2.approx.f32 %0, %1;" : "=f"(r) : "f"(x)); return r;
}
__device__ __forceinline__ float lg2_ap(float x) {
    float r; asm("lg2.approx.f32 %0, %1;" : "=f"(r) : "f"(x)); return r;
}

// ---------------------------------------------------------------------------
// Kernel 1: classify + dense global compaction + self-reset of all counters
// ---------------------------------------------------------------------------
__global__ void __launch_bounds__(256) classify_k(
    const float* __restrict__ p,
    const float* __restrict__ centers,
    const float* __restrict__ radii,
    const float* __restrict__ tfs,
    float* __restrict__ out, int npts) {

    __shared__ int s_thr2_bits;
    __shared__ int s_count;
    __shared__ int s_gbase;

    const int tid = threadIdx.x;
    if (tid == 0) { s_thr2_bits = 0; s_count = 0; }

    int t = blockIdx.x * 256 + tid;
    int base = t * 4;
    float4 va, vb, vc;
    bool inb = base < npts;
    if (inb) {
        const float4* p4 = reinterpret_cast<const float4*>(p);
        int f = t * 3;
        va = p4[f]; vb = p4[f + 1]; vc = p4[f + 2];
    }
    __syncthreads();

    // per-block redundant threshold (fp32, rigorous lower bound on sigma_min)
    if (tid < N_SPH) {
        int i = tid;
        float T[3][3];
        #pragma unroll
        for (int r = 0; r < 3; ++r)
            #pragma unroll
            for (int c = 0; c < 3; ++c)
                T[r][c] = tfs[i * 9 + r * 3 + c] + ((r == c) ? 1.0f : 0.0f);
        float cx = centers[i * 3], cy = centers[i * 3 + 1], cz = centers[i * 3 + 2];
        float rad = radii[i];

        float M00 = 0, M11 = 0, M22 = 0, M01 = 0, M02 = 0, M12 = 0;
        #pragma unroll
        for (int k = 0; k < 3; ++k) {
            float t0 = T[k][0], t1 = T[k][1], t2 = T[k][2];
            M00 = fmaf(t0, t0, M00); M11 = fmaf(t1, t1, M11); M22 = fmaf(t2, t2, M22);
            M01 = fmaf(t0, t1, M01); M02 = fmaf(t0, t2, M02); M12 = fmaf(t1, t2, M12);
        }
        float q  = (M00 + M11 + M22) * (1.0f / 3.0f);
        float a0 = M00 - q, a1 = M11 - q, a2 = M22 - q;
        float p2 = a0 * a0 + a1 * a1 + a2 * a2
                 + 2.0f * (M01 * M01 + M02 * M02 + M12 * M12);
        float lmin = q - 2.001f * sqrtf(fmaxf(p2, 0.0f) * (1.0f / 6.0f)) - 1e-6f;
        float sig  = sqrtf(fmaxf(lmin, 0.0f)) * 0.999f;
        float cn   = sqrtf(cx * cx + cy * cy + cz * cz) * 1.0001f + 1e-7f;
        float num  = 0.601f + cn + rad;   // 0.601 > (ln128 + ln1e6)/32 = 0.5834
        float thr2 = 1e30f;               // sig~0 => no culling (still correct)
        if (sig > 1e-6f) {
            float thr = num / sig;
            thr2 = thr * thr * 1.002f;
        }
        atomicMax(&s_thr2_bits, __float_as_int(thr2));
    }
    __syncthreads();
    float R2 = __int_as_float(s_thr2_bits);

    float x[4], y[4], z[4];
    bool nearf[4] = {false, false, false, false};
    int cnt = 0;
    if (inb) {
        x[0] = va.x; y[0] = va.y; z[0] = va.z;
        x[1] = va.w; y[1] = vb.x; z[1] = vb.y;
        x[2] = vb.z; y[2] = vb.w; z[2] = vc.x;
        x[3] = vc.y; y[3] = vc.z; z[3] = vc.w;
        #pragma unroll
        for (int k = 0; k < 4; ++k) {
            float n2 = fmaf(x[k], x[k], fmaf(y[k], y[k], z[k] * z[k]));
            nearf[k] = n2 < R2;
            if (!nearf[k]) out[base + k] = FASTVAL;
            cnt += nearf[k] ? 1 : 0;
        }
    }

    unsigned mask = 0xffffffffu;
    int lane = tid & 31;
    int incl = cnt;
    #pragma unroll
    for (int d = 1; d < 32; d <<= 1) {
        int v = __shfl_up_sync(mask, incl, d);
        if (lane >= d) incl += v;
    }
    int total = __shfl_sync(mask, incl, 31);
    int wbase = 0;
    if (lane == 0) wbase = (total > 0) ? atomicAdd(&s_count, total) : 0;
    wbase = __shfl_sync(mask, wbase, 0);
    __syncthreads();
    if (tid == 0) s_gbase = (s_count > 0) ? atomicAdd(&g_count, s_count) : 0;
    __syncthreads();

    int off = s_gbase + wbase + incl - cnt;
    #pragma unroll
    for (int k = 0; k < 4; ++k) {
        if (nearf[k]) {
            g_comp[off] = make_float4(x[k], y[k], z[k], __int_as_float(base + k));
            off++;
        }
    }

    __syncthreads();
    if (tid == 0) {
        __threadfence();
        int tk = atomicAdd(&g_done, 1);
        if (tk == (int)gridDim.x - 1) {
            g_total  = g_count;
            g_count  = 0;
            g_done   = 0;
            g_ticket = 0;
            __threadfence();
        }
    }
}

// one sphere's contribution for a packed point-pair; fully inlined, independent
__device__ __forceinline__ void sphere_step(
    const float* __restrict__ sbase, int sp,
    u64 X, u64 Y, u64 Z, float& s0, float& s1) {
    const ulonglong2* C = reinterpret_cast<const ulonglong2*>(sbase + sp * 32);
    ulonglong2 m0 = C[0];  // (t00, t01)
    ulonglong2 m1 = C[1];  // (t02, -cx)
    ulonglong2 m2 = C[2];  // (t10, t11)
    ulonglong2 m3 = C[3];  // (t12, -cy)
    ulonglong2 m4 = C[4];  // (t20, t21)
    ulonglong2 m5 = C[5];  // (t22, -cz)
    u64 bb = reinterpret_cast<const u64*>(C)[12];

    u64 qx = f2fma(m0.x, X, f2fma(m0.y, Y, f2fma(m1.x, Z, m1.y)));
    u64 qy = f2fma(m2.x, X, f2fma(m2.y, Y, f2fma(m3.x, Z, m3.y)));
    u64 qz = f2fma(m4.x, X, f2fma(m4.y, Y, f2fma(m5.x, Z, m5.y)));
    u64 d2 = f2fma(qx, qx, f2fma(qy, qy, f2mul(qz, qz)));

    float2 d  = up2(d2);
    float2 bs = up2(bb);
    s0 += ex2_ap(fmaf(sqrt_ap(d.x), -46.16624130844683f, bs.x));
    s1 += ex2_ap(fmaf(sqrt_ap(d.y), -46.16624130844683f, bs.y));
}

// ---------------------------------------------------------------------------
// Kernel 2: main loop; 4 explicit independent sphere-chains per warp-iter
// ---------------------------------------------------------------------------
__global__ void __launch_bounds__(256) main_k(
    const float* __restrict__ centers,
    const float* __restrict__ radii,
    const float* __restrict__ tfs,
    float* __restrict__ out) {

    __shared__ __align__(16) float shc[N_SPH * 32];

    const int tid = threadIdx.x;
    if (tid < N_SPH) {
        int i = tid;
        float* s = shc + i * 32;
        #pragma unroll
        for (int r = 0; r < 3; ++r) {
            #pragma unroll
            for (int c = 0; c < 3; ++c) {
                float v = tfs[i * 9 + r * 3 + c] + ((r == c) ? 1.0f : 0.0f);
                s[r * 8 + c * 2]     = v;
                s[r * 8 + c * 2 + 1] = v;
            }
            float nc = -centers[i * 3 + r];
            s[r * 8 + 6] = nc;
            s[r * 8 + 7] = nc;
        }
        float b = 46.16624130844683f * radii[i];  // 32*log2(e)*r
        s[24] = b; s[25] = b;
        s[26] = 0.f; s[27] = 0.f; s[28] = 0.f; s[29] = 0.f; s[30] = 0.f; s[31] = 0.f;
    }
    __syncthreads();

    int count = g_total;
    if (count <= 0) return;
    int pairs = (count + 1) >> 1;
    int slabs = (pairs + 31) >> 5;
    int lane  = tid & 31;

    for (;;) {
        int sl = 0;
        if (lane == 0) sl = atomicAdd(&g_ticket, 1);
        sl = __shfl_sync(0xffffffffu, sl, 0);
        if (sl >= slabs) break;

        int j   = (sl << 5) + lane;
        bool act = j < pairs;
        int jj  = act ? j : (pairs - 1);
        int ia  = 2 * jj;
        int ib  = min(2 * jj + 1, count - 1);
        float4 A = g_comp[ia];
        float4 B = g_comp[ib];

        u64 X = pk2(A.x, B.x), Y = pk2(A.y, B.y), Z = pk2(A.z, B.z);

        // 4 independent accumulator pairs -> 4 concurrent dependency chains
        float a0 = 0.f, a1 = 0.f;
        float b0 = 0.f, b1 = 0.f;
        float c0 = 0.f, c1 = 0.f;
        float d0 = 0.f, d1 = 0.f;

        #pragma unroll 2
        for (int sp = 0; sp < N_SPH; sp += 4) {
            sphere_step(shc, sp,     X, Y, Z, a0, a1);
            sphere_step(shc, sp + 1, X, Y, Z, b0, b1);
            sphere_step(shc, sp + 2, X, Y, Z, c0, c1);
            sphere_step(shc, sp + 3, X, Y, Z, d0, d1);
        }

        float s0 = (a0 + b0) + (c0 + d0);
        float s1 = (a1 + b1) + (c1 + d1);

        const float NEG_LN2_32 = -0.021660849392498290f;
        if (act) {
            out[__float_as_int(A.w)] = lg2_ap(fmaxf(s0, 1e-6f)) * NEG_LN2_32;
            if (2 * jj + 1 < count)
                out[__float_as_int(B.w)] = lg2_ap(fmaxf(s1, 1e-6f)) * NEG_LN2_32;
        }
    }
}

extern "C" void kernel_launch(void* const* d_in, const int* in_sizes, int n_in,
                              void* d_out, int out_size) {
    const float* p       = (const float*)d_in[0];
    const float* centers = (const float*)d_in[1];
    const float* radii   = (const float*)d_in[2];
    const float* tfs     = (const float*)d_in[3];
    float* out = (float*)d_out;

    int npts = in_sizes[0] / 3;

    int cblocks = (npts + 1023) / 1024;  // 256 threads x 4 points
    classify_k<<<cblocks, 256>>>(p, centers, radii, tfs, out, npts);

    main_k<<<1184, 256>>>(centers, radii, tfs, out);
}

// round 7
// speedup vs baseline: 1.6979x; 1.6979x over previous
#include <cuda_runtime.h>

#define N_SPH 128
typedef unsigned long long u64;

// -ln(1e-6)/32 : exact output when s clamps at 1e-6
#define FASTVAL 0.4317347049363836f

// dynamic shared memory carve-up (bytes)
#define SHC_BYTES   (N_SPH * 28 * 4)        // 14336: packed consts, 28 floats/sphere
#define SBUF_BYTES  (1024 * 16)             // 16384: compacted points
#define SPART_BYTES (1024 * 8 * 4)          // 32768: 8 sphere-group partials per point
#define SMEM_TOTAL  (SHC_BYTES + SBUF_BYTES + SPART_BYTES)

// ---- packed f32x2 helpers (sm_100+) ----
__device__ __forceinline__ u64 pk2(float lo, float hi) {
    u64 r; asm("mov.b64 %0, {%1, %2};" : "=l"(r) : "f"(lo), "f"(hi)); return r;
}
__device__ __forceinline__ float2 up2(u64 v) {
    float2 f; asm("mov.b64 {%0, %1}, %2;" : "=f"(f.x), "=f"(f.y) : "l"(v)); return f;
}
__device__ __forceinline__ u64 f2fma(u64 a, u64 b, u64 c) {
    u64 d; asm("fma.rn.f32x2 %0, %1, %2, %3;" : "=l"(d) : "l"(a), "l"(b), "l"(c)); return d;
}
__device__ __forceinline__ u64 f2mul(u64 a, u64 b) {
    u64 d; asm("mul.rn.f32x2 %0, %1, %2;" : "=l"(d) : "l"(a), "l"(b)); return d;
}
__device__ __forceinline__ float sqrt_ap(float x) {
    float r; asm("sqrt.approx.f32 %0, %1;" : "=f"(r) : "f"(x)); return r;
}
__device__ __forceinline__ float ex2_ap(float x) {
    float r; asm("ex2.approx.f32 %0, %1;" : "=f"(r) : "f"(x)); return r;
}
__device__ __forceinline__ float lg2_ap(float x) {
    float r; asm("lg2.approx.f32 %0, %1;" : "=f"(r) : "f"(x)); return r;
}

__global__ void __launch_bounds__(256) smoothed_fused(
    const float* __restrict__ p,
    const float* __restrict__ centers,
    const float* __restrict__ radii,
    const float* __restrict__ tfs,
    float* __restrict__ out, int npts) {

    extern __shared__ __align__(16) char dsm[];
    float*  shc   = reinterpret_cast<float*>(dsm);                    // consts
    float4* sbuf  = reinterpret_cast<float4*>(dsm + SHC_BYTES);       // points
    float*  spart = reinterpret_cast<float*>(dsm + SHC_BYTES + SBUF_BYTES);
    __shared__ int s_thr2_bits;
    __shared__ int s_count;

    const int tid = threadIdx.x;
    if (tid == 0) { s_thr2_bits = 0; s_count = 0; }

    // ---- prefetch this thread's 4 points ----
    int t = blockIdx.x * 256 + tid;
    int base = t * 4;
    float4 va, vb, vc;
    bool inb = base < npts;
    if (inb) {
        const float4* p4 = reinterpret_cast<const float4*>(p);
        int f = t * 3;
        va = p4[f]; vb = p4[f + 1]; vc = p4[f + 2];
    }
    __syncthreads();

    // ---- phase A: threads 0..127 build sphere consts + radial threshold ----
    if (tid < N_SPH) {
        int i = tid;
        float T[3][3];
        #pragma unroll
        for (int r = 0; r < 3; ++r)
            #pragma unroll
            for (int c = 0; c < 3; ++c)
                T[r][c] = tfs[i * 9 + r * 3 + c] + ((r == c) ? 1.0f : 0.0f);
        float cx = centers[i * 3], cy = centers[i * 3 + 1], cz = centers[i * 3 + 2];
        float rad = radii[i];

        float* s = shc + i * 28;
        #pragma unroll
        for (int r = 0; r < 3; ++r) {
            float cs3[4] = {T[r][0], T[r][1], T[r][2],
                            (r == 0 ? -cx : (r == 1 ? -cy : -cz))};
            #pragma unroll
            for (int c = 0; c < 4; ++c) {
                s[(r * 4 + c) * 2]     = cs3[c];
                s[(r * 4 + c) * 2 + 1] = cs3[c];
            }
        }
        float b = 46.16624130844683f * rad;  // 32*log2(e)*r
        s[24] = b; s[25] = b; s[26] = 0.f; s[27] = 0.f;

        // sigma_min lower bound: lambda_min(T^T T) >= q - 2*sqrt(p2/6)
        float M00 = 0, M11 = 0, M22 = 0, M01 = 0, M02 = 0, M12 = 0;
        #pragma unroll
        for (int k = 0; k < 3; ++k) {
            float t0 = T[k][0], t1 = T[k][1], t2 = T[k][2];
            M00 = fmaf(t0, t0, M00); M11 = fmaf(t1, t1, M11); M22 = fmaf(t2, t2, M22);
            M01 = fmaf(t0, t1, M01); M02 = fmaf(t0, t2, M02); M12 = fmaf(t1, t2, M12);
        }
        float q  = (M00 + M11 + M22) * (1.0f / 3.0f);
        float a0 = M00 - q, a1 = M11 - q, a2 = M22 - q;
        float p2 = a0 * a0 + a1 * a1 + a2 * a2
                 + 2.0f * (M01 * M01 + M02 * M02 + M12 * M12);
        float lmin = q - 2.001f * sqrtf(fmaxf(p2, 0.0f) * (1.0f / 6.0f)) - 1e-6f;
        float sig  = sqrtf(fmaxf(lmin, 0.0f)) * 0.999f;
        float cn   = sqrtf(cx * cx + cy * cy + cz * cz) * 1.0001f + 1e-7f;
        float num  = 0.601f + cn + rad;   // 0.601 > (ln128+ln1e6)/32 = 0.5834
        float thr2 = 1e30f;               // sig~0 => no culling (still correct)
        if (sig > 1e-6f) {
            float thr = num / sig;
            thr2 = thr * thr * 1.002f;
        }
        atomicMax(&s_thr2_bits, __float_as_int(thr2));
    }
    __syncthreads();
    float R2 = __int_as_float(s_thr2_bits);

    // ---- phase B: classify 4 points, compact near ones into shared ----
    float x[4], y[4], z[4];
    bool nearf[4] = {false, false, false, false};
    int cnt = 0;
    if (inb) {
        x[0] = va.x; y[0] = va.y; z[0] = va.z;
        x[1] = va.w; y[1] = vb.x; z[1] = vb.y;
        x[2] = vb.z; y[2] = vb.w; z[2] = vc.x;
        x[3] = vc.y; y[3] = vc.z; z[3] = vc.w;
        #pragma unroll
        for (int k = 0; k < 4; ++k) {
            float n2 = fmaf(x[k], x[k], fmaf(y[k], y[k], z[k] * z[k]));
            nearf[k] = n2 < R2;
            if (!nearf[k]) out[base + k] = FASTVAL;
            cnt += nearf[k] ? 1 : 0;
        }
    }
    unsigned mask = 0xffffffffu;
    int lane = tid & 31;
    int incl = cnt;
    #pragma unroll
    for (int d = 1; d < 32; d <<= 1) {
        int v = __shfl_up_sync(mask, incl, d);
        if (lane >= d) incl += v;
    }
    int total = __shfl_sync(mask, incl, 31);
    int wbase = 0;
    if (lane == 0) wbase = (total > 0) ? atomicAdd(&s_count, total) : 0;
    wbase = __shfl_sync(mask, wbase, 0);
    int off = wbase + incl - cnt;
    #pragma unroll
    for (int k = 0; k < 4; ++k) {
        if (nearf[k]) {
            sbuf[off] = make_float4(x[k], y[k], z[k], __int_as_float(base + k));
            off++;
        }
    }
    __syncthreads();

    // ---- phase C: units = (pair j, sphere-group g of 16 spheres) ----
    // warp-mates share g (broadcast consts): j = (u>>8)*32 + (u&31), g = (u>>5)&7
    int count = s_count;
    int pairs = (count + 1) >> 1;
    int total_u = ((pairs + 31) >> 5) << 8;   // pairs rounded to 32, x8 groups

    for (int u = tid; u < total_u; u += 256) {
        int j = ((u >> 8) << 5) | (u & 31);
        int g = (u >> 5) & 7;
        if (j >= pairs) continue;

        int ia = 2 * j;
        int ib = min(2 * j + 1, count - 1);
        float4 A = sbuf[ia];
        float4 B = sbuf[ib];

        u64 X = pk2(A.x, B.x), Y = pk2(A.y, B.y), Z = pk2(A.z, B.z);
        float s0 = 0.f, s1 = 0.f;

        const float* cb = shc + g * (16 * 28);
        #pragma unroll 4
        for (int sp = 0; sp < 16; ++sp) {
            const ulonglong2* C = reinterpret_cast<const ulonglong2*>(cb + sp * 28);
            ulonglong2 m0 = C[0];  // (t00, t01)
            ulonglong2 m1 = C[1];  // (t02, -cx)
            ulonglong2 m2 = C[2];  // (t10, t11)
            ulonglong2 m3 = C[3];  // (t12, -cy)
            ulonglong2 m4 = C[4];  // (t20, t21)
            ulonglong2 m5 = C[5];  // (t22, -cz)
            u64 bb = reinterpret_cast<const u64*>(C)[12];

            u64 qx = f2fma(m0.x, X, f2fma(m0.y, Y, f2fma(m1.x, Z, m1.y)));
            u64 qy = f2fma(m2.x, X, f2fma(m2.y, Y, f2fma(m3.x, Z, m3.y)));
            u64 qz = f2fma(m4.x, X, f2fma(m4.y, Y, f2fma(m5.x, Z, m5.y)));
            u64 d2 = f2fma(qx, qx, f2fma(qy, qy, f2mul(qz, qz)));

            float2 d  = up2(d2);
            float2 bs = up2(bb);
            s0 += ex2_ap(fmaf(sqrt_ap(d.x), -46.16624130844683f, bs.x));
            s1 += ex2_ap(fmaf(sqrt_ap(d.y), -46.16624130844683f, bs.y));
        }

        spart[ia * 8 + g] = s0;
        if (2 * j + 1 < count) spart[ib * 8 + g] = s1;
    }
    __syncthreads();

    // ---- phase D: finalize — fixed-order combine of the 8 partials ----
    const float NEG_LN2_32 = -0.021660849392498290f;
    for (int pt = tid; pt < count; pt += 256) {
        const float* pp = spart + pt * 8;
        float s = ((pp[0] + pp[1]) + (pp[2] + pp[3]))
                + ((pp[4] + pp[5]) + (pp[6] + pp[7]));
        out[__float_as_int(sbuf[pt].w)] = lg2_ap(fmaxf(s, 1e-6f)) * NEG_LN2_32;
    }
}

extern "C" void kernel_launch(void* const* d_in, const int* in_sizes, int n_in,
                              void* d_out, int out_size) {
    const float* p       = (const float*)d_in[0];
    const float* centers = (const float*)d_in[1];
    const float* radii   = (const float*)d_in[2];
    const float* tfs     = (const float*)d_in[3];
    float* out = (float*)d_out;

    int npts = in_sizes[0] / 3;

    static int attr_set = 0;
    if (!attr_set) {
        cudaFuncSetAttribute(smoothed_fused,
                             cudaFuncAttributeMaxDynamicSharedMemorySize, SMEM_TOTAL);
        attr_set = 1;
    }

    int blocks = (npts + 1023) / 1024;  // 256 threads x 4 points
    smoothed_fused<<<blocks, 256, SMEM_TOTAL>>>(p, centers, radii, tfs, out, npts);
}